// round 1
// baseline (speedup 1.0000x reference)
#include <cuda_runtime.h>
#include <math.h>

#define SUBNETS 64
#define NH1 10
#define NH2 6
#define GRIDN 101
#define K_INT 208            // intervals
#define KNOTS 209            // knots = K_INT + 1
#define TAB_LO  (-6.5f)
#define TAB_DX  (0.0625f)    // 1/16
#define TAB_INVDX (16.0f)

// Piecewise-cubic table: per (subnet, interval) coefficients (c0,c1,c2,c3) in
// local coordinate t in [0,1). Normalization (x - mean)/norm is pre-folded.
__device__ float4 g_table[SUBNETS * K_INT];

// Accurate MLP evaluation (value + analytic derivative) for one subnet.
__device__ __forceinline__ void mlp_eval(
    float x, int s,
    const float* __restrict__ W1, const float* __restrict__ b1,
    const float* __restrict__ W2, const float* __restrict__ b2,
    const float* __restrict__ W3, const float* __restrict__ b3,
    float* f_out, float* d_out)
{
    float h1[NH1], dh1[NH1];
#pragma unroll
    for (int h = 0; h < NH1; h++) {
        float w = W1[s * NH1 + h];
        float p = fmaf(w, x, b1[s * NH1 + h]);
        float t = tanhf(p);
        h1[h]  = t;
        dh1[h] = (1.0f - t * t) * w;
    }
    float f = b3[s];
    float d = 0.0f;
#pragma unroll
    for (int k = 0; k < NH2; k++) {
        float a  = b2[s * NH2 + k];
        float da = 0.0f;
#pragma unroll
        for (int h = 0; h < NH1; h++) {
            float w2 = W2[(s * NH1 + h) * NH2 + k];
            a  = fmaf(h1[h],  w2, a);
            da = fmaf(dh1[h], w2, da);
        }
        float t  = tanhf(a);
        float w3 = W3[s * NH2 + k];
        f = fmaf(t, w3, f);
        d = fmaf((1.0f - t * t) * da, w3, d);
    }
    *f_out = f;
    *d_out = d;
}

// One block per subnet: grid stats (mean / clamped std) + Hermite coefficients
// with normalization folded in.
__global__ __launch_bounds__(256)
void setup_kernel(const float* __restrict__ W1, const float* __restrict__ b1,
                  const float* __restrict__ W2, const float* __restrict__ b2,
                  const float* __restrict__ W3, const float* __restrict__ b3)
{
    __shared__ float sh_g[GRIDN];
    __shared__ float sh_f[KNOTS];
    __shared__ float sh_d[KNOTS];
    __shared__ float sh_mean, sh_inv;

    const int s = blockIdx.x;
    const int t = threadIdx.x;

    if (t < GRIDN) {
        // jnp.linspace(-1, 1, 101)
        float x = fmaf((float)t, 0.02f, -1.0f);
        float f, d;
        mlp_eval(x, s, W1, b1, W2, b2, W3, b3, &f, &d);
        sh_g[t] = f;
    }
    if (t < KNOTS) {
        float x = fmaf((float)t, TAB_DX, TAB_LO);
        float f, d;
        mlp_eval(x, s, W1, b1, W2, b2, W3, b3, &f, &d);
        sh_f[t] = f;
        sh_d[t] = d;
    }
    __syncthreads();

    if (t == 0) {
        double m = 0.0, m2 = 0.0;
        for (int i = 0; i < GRIDN; i++) {
            double g = (double)sh_g[i];
            m  += g;
            m2 += g * g;
        }
        m  /= (double)GRIDN;
        m2 /= (double)GRIDN;
        double var = m2 - m * m;
        if (var < 0.0) var = 0.0;
        double sd = sqrt(var);
        if (sd < 1e-10) sd = 1e-10;
        sh_mean = (float)m;
        sh_inv  = (float)(1.0 / sd);
    }
    __syncthreads();

    if (t < K_INT) {
        const float mean = sh_mean;
        const float inv  = sh_inv;
        float f0 = (sh_f[t]     - mean) * inv;
        float f1 = (sh_f[t + 1] - mean) * inv;
        float m0 = sh_d[t]     * inv * TAB_DX;
        float m1 = sh_d[t + 1] * inv * TAB_DX;
        float c2 = 3.0f * (f1 - f0) - 2.0f * m0 - m1;
        float c3 = 2.0f * (f0 - f1) + m0 + m1;
        g_table[s * K_INT + t] = make_float4(f0, m0, c2, c3);
    }
}

// Main kernel: 4 elements per thread per iteration.
// Per-thread subnet identities are loop-invariant (stride % 64 == 0), so
// idx gather + table row pointers hoist out of the loop.
__global__ __launch_bounds__(256)
void eval_kernel(const float* __restrict__ in, const int* __restrict__ idx,
                 float* __restrict__ out, int n4)
{
    const int tid      = blockIdx.x * blockDim.x + threadIdx.x;
    const int nthreads = gridDim.x * blockDim.x;   // multiple of 16

    const int base_s = (tid * 4) & 63;             // multiple of 4, <= 60
    const float4* rows[4];
    int off[4];
#pragma unroll
    for (int u = 0; u < 4; u++) {
        int s   = base_s + u;                      // < 64, no wrap
        rows[u] = &g_table[s * K_INT];
        off[u]  = u + idx[s] - s;                  // input offset vs 4*i4
    }

    for (int i4 = tid; i4 < n4; i4 += nthreads) {
        const int b4 = i4 << 2;
        float r[4];
#pragma unroll
        for (int u = 0; u < 4; u++) {
            float x  = __ldg(in + b4 + off[u]);
            float q  = fmaf(x, TAB_INVDX, 104.0f); // (x + 6.5) * 16
            float jf = floorf(q);
            jf = fminf(fmaxf(jf, 0.0f), (float)(K_INT - 1));
            float tt = q - jf;
            float4 c = __ldg(rows[u] + (int)jf);
            r[u] = fmaf(fmaf(fmaf(c.w, tt, c.z), tt, c.y), tt, c.x);
        }
        reinterpret_cast<float4*>(out)[i4] = make_float4(r[0], r[1], r[2], r[3]);
    }
}

extern "C" void kernel_launch(void* const* d_in, const int* in_sizes, int n_in,
                              void* d_out, int out_size)
{
    const float* inputs = (const float*)d_in[0];
    const int*   idx    = (const int*)  d_in[1];
    const float* W1     = (const float*)d_in[2];
    const float* b1     = (const float*)d_in[3];
    const float* W2     = (const float*)d_in[4];
    const float* b2     = (const float*)d_in[5];
    const float* W3     = (const float*)d_in[6];
    const float* b3     = (const float*)d_in[7];
    float*       outp   = (float*)d_out;

    setup_kernel<<<SUBNETS, 256>>>(W1, b1, W2, b2, W3, b3);

    const int n4 = out_size >> 2;                  // 2,097,152
    eval_kernel<<<2048, 256>>>(inputs, idx, outp, n4);
}

// round 2
// speedup vs baseline: 1.1300x; 1.1300x over previous
#include <cuda_runtime.h>
#include <math.h>

#define SUBNETS 64
#define NH1 10
#define NH2 6
#define GRIDN 101
#define K_INT 208            // intervals
#define KNOTS 209            // knots = K_INT + 1
#define ROWP 209             // padded row stride (float4 units) in smem
#define TAB_LO  (-6.5f)
#define TAB_DX  (0.0625f)    // 1/16
#define TAB_INVDX (16.0f)

#define EVAL_BLOCK 1024
#define EVAL_GRID  148
#define SMEM_BYTES (SUBNETS * ROWP * (int)sizeof(float4))   // 214,016 B

// Piecewise-cubic table: per (subnet, interval) coefficients (c0,c1,c2,c3) in
// local coordinate t in [0,1). Normalization (x - mean)/norm is pre-folded.
__device__ float4 g_table[SUBNETS * K_INT];

// Accurate MLP evaluation (value + analytic derivative) for one subnet.
__device__ __forceinline__ void mlp_eval(
    float x, int s,
    const float* __restrict__ W1, const float* __restrict__ b1,
    const float* __restrict__ W2, const float* __restrict__ b2,
    const float* __restrict__ W3, const float* __restrict__ b3,
    float* f_out, float* d_out)
{
    float h1[NH1], dh1[NH1];
#pragma unroll
    for (int h = 0; h < NH1; h++) {
        float w = W1[s * NH1 + h];
        float p = fmaf(w, x, b1[s * NH1 + h]);
        float t = tanhf(p);
        h1[h]  = t;
        dh1[h] = (1.0f - t * t) * w;
    }
    float f = b3[s];
    float d = 0.0f;
#pragma unroll
    for (int k = 0; k < NH2; k++) {
        float a  = b2[s * NH2 + k];
        float da = 0.0f;
#pragma unroll
        for (int h = 0; h < NH1; h++) {
            float w2 = W2[(s * NH1 + h) * NH2 + k];
            a  = fmaf(h1[h],  w2, a);
            da = fmaf(dh1[h], w2, da);
        }
        float t  = tanhf(a);
        float w3 = W3[s * NH2 + k];
        f = fmaf(t, w3, f);
        d = fmaf((1.0f - t * t) * da, w3, d);
    }
    *f_out = f;
    *d_out = d;
}

// One block per subnet: grid stats (mean / clamped std) + Hermite coefficients
// with normalization folded in.
__global__ __launch_bounds__(256)
void setup_kernel(const float* __restrict__ W1, const float* __restrict__ b1,
                  const float* __restrict__ W2, const float* __restrict__ b2,
                  const float* __restrict__ W3, const float* __restrict__ b3)
{
    __shared__ float sh_g[GRIDN];
    __shared__ float sh_f[KNOTS];
    __shared__ float sh_d[KNOTS];
    __shared__ float sh_mean, sh_inv;

    const int s = blockIdx.x;
    const int t = threadIdx.x;

    if (t < GRIDN) {
        // jnp.linspace(-1, 1, 101)
        float x = fmaf((float)t, 0.02f, -1.0f);
        float f, d;
        mlp_eval(x, s, W1, b1, W2, b2, W3, b3, &f, &d);
        sh_g[t] = f;
    }
    if (t < KNOTS) {
        float x = fmaf((float)t, TAB_DX, TAB_LO);
        float f, d;
        mlp_eval(x, s, W1, b1, W2, b2, W3, b3, &f, &d);
        sh_f[t] = f;
        sh_d[t] = d;
    }
    __syncthreads();

    if (t == 0) {
        double m = 0.0, m2 = 0.0;
        for (int i = 0; i < GRIDN; i++) {
            double g = (double)sh_g[i];
            m  += g;
            m2 += g * g;
        }
        m  /= (double)GRIDN;
        m2 /= (double)GRIDN;
        double var = m2 - m * m;
        if (var < 0.0) var = 0.0;
        double sd = sqrt(var);
        if (sd < 1e-10) sd = 1e-10;
        sh_mean = (float)m;
        sh_inv  = (float)(1.0 / sd);
    }
    __syncthreads();

    if (t < K_INT) {
        const float mean = sh_mean;
        const float inv  = sh_inv;
        float f0 = (sh_f[t]     - mean) * inv;
        float f1 = (sh_f[t + 1] - mean) * inv;
        float m0 = sh_d[t]     * inv * TAB_DX;
        float m1 = sh_d[t + 1] * inv * TAB_DX;
        float c2 = 3.0f * (f1 - f0) - 2.0f * m0 - m1;
        float c3 = 2.0f * (f0 - f1) + m0 + m1;
        g_table[s * K_INT + t] = make_float4(f0, m0, c2, c3);
    }
}

__device__ __forceinline__ float cubic_lookup(const float4* __restrict__ tab,
                                              int row_base, float x)
{
    float q  = fmaf(x, TAB_INVDX, 104.0f);   // (x + 6.5) * 16
    float jf = floorf(q);
    jf = fminf(fmaxf(jf, 0.0f), (float)(K_INT - 1));
    float tt = q - jf;
    float4 c = tab[row_base + (int)jf];
    return fmaf(fmaf(fmaf(c.w, tt, c.z), tt, c.y), tt, c.x);
}

// Main kernel: table staged in shared memory (214 KB, 1 block/SM).
// Each thread owns 4 consecutive output elements per iteration (4 fixed
// subnets); identity-idx fast path uses one coalesced float4 input load.
__global__ __launch_bounds__(EVAL_BLOCK, 1)
void eval_kernel(const float* __restrict__ in, const int* __restrict__ idx,
                 float* __restrict__ out, int n4)
{
    extern __shared__ float4 tab[];          // [SUBNETS][ROWP]

    // Cooperative stage: global table -> padded smem layout.
    for (int i = threadIdx.x; i < SUBNETS * K_INT; i += EVAL_BLOCK) {
        int s = i / K_INT;
        int j = i - s * K_INT;
        tab[s * ROWP + j] = g_table[i];
    }
    __syncthreads();

    const int tid      = blockIdx.x * EVAL_BLOCK + threadIdx.x;
    const int nthreads = EVAL_GRID * EVAL_BLOCK;

    const int base_s = (tid * 4) & 63;       // multiple of 4, <= 60
    int rowb[4];
    int off[4];
#pragma unroll
    for (int u = 0; u < 4; u++) {
        int s   = base_s + u;                // < 64, no wrap
        rowb[u] = s * ROWP;
        off[u]  = u + idx[s] - s;            // input offset vs 4*i4
    }

    const bool identity = (off[0] == 0) & (off[1] == 1) &
                          (off[2] == 2) & (off[3] == 3);

    if (identity) {
        for (int i4 = tid; i4 < n4; i4 += nthreads) {
            float4 xv = __ldg(reinterpret_cast<const float4*>(in) + i4);
            float4 r;
            r.x = cubic_lookup(tab, rowb[0], xv.x);
            r.y = cubic_lookup(tab, rowb[1], xv.y);
            r.z = cubic_lookup(tab, rowb[2], xv.z);
            r.w = cubic_lookup(tab, rowb[3], xv.w);
            reinterpret_cast<float4*>(out)[i4] = r;
        }
    } else {
        for (int i4 = tid; i4 < n4; i4 += nthreads) {
            const int b4 = i4 << 2;
            float r[4];
#pragma unroll
            for (int u = 0; u < 4; u++) {
                float x = __ldg(in + b4 + off[u]);
                r[u] = cubic_lookup(tab, rowb[u], x);
            }
            reinterpret_cast<float4*>(out)[i4] =
                make_float4(r[0], r[1], r[2], r[3]);
        }
    }
}

extern "C" void kernel_launch(void* const* d_in, const int* in_sizes, int n_in,
                              void* d_out, int out_size)
{
    const float* inputs = (const float*)d_in[0];
    const int*   idx    = (const int*)  d_in[1];
    const float* W1     = (const float*)d_in[2];
    const float* b1     = (const float*)d_in[3];
    const float* W2     = (const float*)d_in[4];
    const float* b2     = (const float*)d_in[5];
    const float* W3     = (const float*)d_in[6];
    const float* b3     = (const float*)d_in[7];
    float*       outp   = (float*)d_out;

    // Opt in to >48KB dynamic shared memory (idempotent, not a stream op).
    cudaFuncSetAttribute(eval_kernel,
                         cudaFuncAttributeMaxDynamicSharedMemorySize,
                         SMEM_BYTES);

    setup_kernel<<<SUBNETS, 256>>>(W1, b1, W2, b2, W3, b3);

    const int n4 = out_size >> 2;            // 2,097,152
    eval_kernel<<<EVAL_GRID, EVAL_BLOCK, SMEM_BYTES>>>(inputs, idx, outp, n4);
}

// round 3
// speedup vs baseline: 1.1725x; 1.0376x over previous
#include <cuda_runtime.h>
#include <math.h>

#define SUBNETS 64
#define NH1 10
#define NH2 6
#define GRIDN 101
#define K_INT 208            // intervals
#define KNOTS 209            // knots = K_INT + 1
#define ROWP 209             // padded row stride (float4 units) in smem
#define TAB_LO  (-6.5f)
#define TAB_DX  (0.0625f)    // 1/16
#define TAB_INVDX (16.0f)

#define EVAL_BLOCK 1024
#define EVAL_GRID  148
#define SMEM_BYTES (SUBNETS * ROWP * (int)sizeof(float4))   // 214,016 B

// Piecewise-cubic table: per (subnet, interval) coefficients (c0,c1,c2,c3) in
// local coordinate t in [0,1). Normalization (x - mean)/norm is pre-folded.
__device__ float4 g_table[SUBNETS * K_INT];

// Accurate MLP evaluation (value + analytic derivative) for one subnet.
__device__ __forceinline__ void mlp_eval(
    float x, int s,
    const float* __restrict__ W1, const float* __restrict__ b1,
    const float* __restrict__ W2, const float* __restrict__ b2,
    const float* __restrict__ W3, const float* __restrict__ b3,
    float* f_out, float* d_out)
{
    float h1[NH1], dh1[NH1];
#pragma unroll
    for (int h = 0; h < NH1; h++) {
        float w = W1[s * NH1 + h];
        float p = fmaf(w, x, b1[s * NH1 + h]);
        float t = tanhf(p);
        h1[h]  = t;
        dh1[h] = (1.0f - t * t) * w;
    }
    float f = b3[s];
    float d = 0.0f;
#pragma unroll
    for (int k = 0; k < NH2; k++) {
        float a  = b2[s * NH2 + k];
        float da = 0.0f;
#pragma unroll
        for (int h = 0; h < NH1; h++) {
            float w2 = W2[(s * NH1 + h) * NH2 + k];
            a  = fmaf(h1[h],  w2, a);
            da = fmaf(dh1[h], w2, da);
        }
        float t  = tanhf(a);
        float w3 = W3[s * NH2 + k];
        f = fmaf(t, w3, f);
        d = fmaf((1.0f - t * t) * da, w3, d);
    }
    *f_out = f;
    *d_out = d;
}

// One block per subnet: grid stats (mean / clamped std) + Hermite coefficients
// with normalization folded in.
__global__ __launch_bounds__(256)
void setup_kernel(const float* __restrict__ W1, const float* __restrict__ b1,
                  const float* __restrict__ W2, const float* __restrict__ b2,
                  const float* __restrict__ W3, const float* __restrict__ b3)
{
    __shared__ float sh_g[GRIDN];
    __shared__ float sh_f[KNOTS];
    __shared__ float sh_d[KNOTS];
    __shared__ float sh_mean, sh_inv;

    const int s = blockIdx.x;
    const int t = threadIdx.x;

    if (t < GRIDN) {
        float x = fmaf((float)t, 0.02f, -1.0f);   // linspace(-1,1,101)
        float f, d;
        mlp_eval(x, s, W1, b1, W2, b2, W3, b3, &f, &d);
        sh_g[t] = f;
    }
    if (t < KNOTS) {
        float x = fmaf((float)t, TAB_DX, TAB_LO);
        float f, d;
        mlp_eval(x, s, W1, b1, W2, b2, W3, b3, &f, &d);
        sh_f[t] = f;
        sh_d[t] = d;
    }
    __syncthreads();

    if (t == 0) {
        double m = 0.0, m2 = 0.0;
        for (int i = 0; i < GRIDN; i++) {
            double g = (double)sh_g[i];
            m  += g;
            m2 += g * g;
        }
        m  /= (double)GRIDN;
        m2 /= (double)GRIDN;
        double var = m2 - m * m;
        if (var < 0.0) var = 0.0;
        double sd = sqrt(var);
        if (sd < 1e-10) sd = 1e-10;
        sh_mean = (float)m;
        sh_inv  = (float)(1.0 / sd);
    }
    __syncthreads();

    if (t < K_INT) {
        const float mean = sh_mean;
        const float inv  = sh_inv;
        float f0 = (sh_f[t]     - mean) * inv;
        float f1 = (sh_f[t + 1] - mean) * inv;
        float m0 = sh_d[t]     * inv * TAB_DX;
        float m1 = sh_d[t + 1] * inv * TAB_DX;
        float c2 = 3.0f * (f1 - f0) - 2.0f * m0 - m1;
        float c3 = 2.0f * (f0 - f1) + m0 + m1;
        g_table[s * K_INT + t] = make_float4(f0, m0, c2, c3);
    }
}

__device__ __forceinline__ float cubic_lookup(const float4* __restrict__ tab,
                                              int row_base, float x)
{
    float q  = fmaf(x, TAB_INVDX, 104.0f);   // (x + 6.5) * 16
    float jf = floorf(q);
    jf = fminf(fmaxf(jf, 0.0f), (float)(K_INT - 1));
    float tt = q - jf;
    float4 c = tab[row_base + (int)jf];
    return fmaf(fmaf(fmaf(c.w, tt, c.z), tt, c.y), tt, c.x);
}

// Main kernel: table staged in shared memory (214 KB, 1 block/SM).
// Identity-idx fast path: software-pipelined, 2 float4 per thread per
// iteration (8 independent table lookups + 2 LDG.128 in flight) so the
// global-load latency and LDS latency overlap with compute.
__global__ __launch_bounds__(EVAL_BLOCK, 1)
void eval_kernel(const float* __restrict__ in, const int* __restrict__ idx,
                 float* __restrict__ out, int n4)
{
    extern __shared__ float4 tab[];          // [SUBNETS][ROWP]

    for (int i = threadIdx.x; i < SUBNETS * K_INT; i += EVAL_BLOCK) {
        int s = i / K_INT;
        int j = i - s * K_INT;
        tab[s * ROWP + j] = g_table[i];
    }
    __syncthreads();

    const int tid      = blockIdx.x * EVAL_BLOCK + threadIdx.x;
    const int nthreads = EVAL_GRID * EVAL_BLOCK;

    const int base_s = (tid * 4) & 63;       // multiple of 4, <= 60
    int rowb[4];
    int off[4];
#pragma unroll
    for (int u = 0; u < 4; u++) {
        int s   = base_s + u;                // < 64, no wrap
        rowb[u] = s * ROWP;
        off[u]  = u + idx[s] - s;            // input offset vs 4*i4
    }

    const bool identity = (off[0] == 0) & (off[1] == 1) &
                          (off[2] == 2) & (off[3] == 3);

    if (identity) {
        const float4* __restrict__ in4 = reinterpret_cast<const float4*>(in);
        float4* __restrict__ out4      = reinterpret_cast<float4*>(out);

        // n4 = 2^21, nthreads = 151552 -> ~13.8 iters; process 2 per loop.
        int ia = tid;
        int ib = tid + nthreads;

        float4 xa, xb;
        bool va = (ia < n4), vb = (ib < n4);
        if (va) xa = __ldg(in4 + ia);
        if (vb) xb = __ldg(in4 + ib);

        while (va) {
            // Prefetch next pair before touching this pair's data.
            int na = ia + 2 * nthreads;
            int nb = ib + 2 * nthreads;
            float4 pa, pb;
            bool pva = (na < n4), pvb = (nb < n4);
            if (pva) pa = __ldg(in4 + na);
            if (pvb) pb = __ldg(in4 + nb);

            float4 ra, rb;
            ra.x = cubic_lookup(tab, rowb[0], xa.x);
            ra.y = cubic_lookup(tab, rowb[1], xa.y);
            ra.z = cubic_lookup(tab, rowb[2], xa.z);
            ra.w = cubic_lookup(tab, rowb[3], xa.w);
            if (vb) {
                rb.x = cubic_lookup(tab, rowb[0], xb.x);
                rb.y = cubic_lookup(tab, rowb[1], xb.y);
                rb.z = cubic_lookup(tab, rowb[2], xb.z);
                rb.w = cubic_lookup(tab, rowb[3], xb.w);
            }
            out4[ia] = ra;
            if (vb) out4[ib] = rb;

            ia = na; ib = nb; xa = pa; xb = pb; va = pva; vb = pvb;
        }
    } else {
        for (int i4 = tid; i4 < n4; i4 += nthreads) {
            const int b4 = i4 << 2;
            float r[4];
#pragma unroll
            for (int u = 0; u < 4; u++) {
                float x = __ldg(in + b4 + off[u]);
                r[u] = cubic_lookup(tab, rowb[u], x);
            }
            reinterpret_cast<float4*>(out)[i4] =
                make_float4(r[0], r[1], r[2], r[3]);
        }
    }
}

extern "C" void kernel_launch(void* const* d_in, const int* in_sizes, int n_in,
                              void* d_out, int out_size)
{
    const float* inputs = (const float*)d_in[0];
    const int*   idx    = (const int*)  d_in[1];
    const float* W1     = (const float*)d_in[2];
    const float* b1     = (const float*)d_in[3];
    const float* W2     = (const float*)d_in[4];
    const float* b2     = (const float*)d_in[5];
    const float* W3     = (const float*)d_in[6];
    const float* b3     = (const float*)d_in[7];
    float*       outp   = (float*)d_out;

    cudaFuncSetAttribute(eval_kernel,
                         cudaFuncAttributeMaxDynamicSharedMemorySize,
                         SMEM_BYTES);

    setup_kernel<<<SUBNETS, 256>>>(W1, b1, W2, b2, W3, b3);

    const int n4 = out_size >> 2;            // 2,097,152
    eval_kernel<<<EVAL_GRID, EVAL_BLOCK, SMEM_BYTES>>>(inputs, idx, outp, n4);
}

// round 4
// speedup vs baseline: 1.1771x; 1.0039x over previous
#include <cuda_runtime.h>
#include <math.h>

#define SUBNETS 64
#define NH1 10
#define NH2 6
#define GRIDN 101
#define K_INT 104            // intervals (delta = 1/8)
#define KNOTS 105            // knots = K_INT + 1
#define ROWP 105             // padded row stride (float4 units) in smem
#define TAB_LO  (-6.5f)
#define TAB_DX  (0.125f)     // 1/8
#define TAB_INVDX (8.0f)
#define TAB_BIAS  (52.0f)    // 6.5 * 8

#define EVAL_BLOCK 1024
#define EVAL_GRID  296       // 2 blocks per SM (148 SMs)
#define SMEM_BYTES (SUBNETS * ROWP * (int)sizeof(float4))   // 107,520 B

// Piecewise-cubic table: per (subnet, interval) coefficients (c0,c1,c2,c3) in
// local coordinate t in [0,1). Normalization (x - mean)/norm is pre-folded.
__device__ float4 g_table[SUBNETS * K_INT];

// Accurate MLP evaluation (value + analytic derivative) for one subnet.
__device__ __forceinline__ void mlp_eval(
    float x, int s,
    const float* __restrict__ W1, const float* __restrict__ b1,
    const float* __restrict__ W2, const float* __restrict__ b2,
    const float* __restrict__ W3, const float* __restrict__ b3,
    float* f_out, float* d_out)
{
    float h1[NH1], dh1[NH1];
#pragma unroll
    for (int h = 0; h < NH1; h++) {
        float w = W1[s * NH1 + h];
        float p = fmaf(w, x, b1[s * NH1 + h]);
        float t = tanhf(p);
        h1[h]  = t;
        dh1[h] = (1.0f - t * t) * w;
    }
    float f = b3[s];
    float d = 0.0f;
#pragma unroll
    for (int k = 0; k < NH2; k++) {
        float a  = b2[s * NH2 + k];
        float da = 0.0f;
#pragma unroll
        for (int h = 0; h < NH1; h++) {
            float w2 = W2[(s * NH1 + h) * NH2 + k];
            a  = fmaf(h1[h],  w2, a);
            da = fmaf(dh1[h], w2, da);
        }
        float t  = tanhf(a);
        float w3 = W3[s * NH2 + k];
        f = fmaf(t, w3, f);
        d = fmaf((1.0f - t * t) * da, w3, d);
    }
    *f_out = f;
    *d_out = d;
}

// One block per subnet: grid stats (mean / clamped std) + Hermite coefficients
// with normalization folded in.
__global__ __launch_bounds__(256)
void setup_kernel(const float* __restrict__ W1, const float* __restrict__ b1,
                  const float* __restrict__ W2, const float* __restrict__ b2,
                  const float* __restrict__ W3, const float* __restrict__ b3)
{
    __shared__ float sh_g[GRIDN];
    __shared__ float sh_f[KNOTS];
    __shared__ float sh_d[KNOTS];
    __shared__ float sh_mean, sh_inv;

    const int s = blockIdx.x;
    const int t = threadIdx.x;

    if (t < GRIDN) {
        float x = fmaf((float)t, 0.02f, -1.0f);   // linspace(-1,1,101)
        float f, d;
        mlp_eval(x, s, W1, b1, W2, b2, W3, b3, &f, &d);
        sh_g[t] = f;
    }
    if (t < KNOTS) {
        float x = fmaf((float)t, TAB_DX, TAB_LO);
        float f, d;
        mlp_eval(x, s, W1, b1, W2, b2, W3, b3, &f, &d);
        sh_f[t] = f;
        sh_d[t] = d;
    }
    __syncthreads();

    if (t == 0) {
        double m = 0.0, m2 = 0.0;
        for (int i = 0; i < GRIDN; i++) {
            double g = (double)sh_g[i];
            m  += g;
            m2 += g * g;
        }
        m  /= (double)GRIDN;
        m2 /= (double)GRIDN;
        double var = m2 - m * m;
        if (var < 0.0) var = 0.0;
        double sd = sqrt(var);
        if (sd < 1e-10) sd = 1e-10;
        sh_mean = (float)m;
        sh_inv  = (float)(1.0 / sd);
    }
    __syncthreads();

    if (t < K_INT) {
        const float mean = sh_mean;
        const float inv  = sh_inv;
        float f0 = (sh_f[t]     - mean) * inv;
        float f1 = (sh_f[t + 1] - mean) * inv;
        float m0 = sh_d[t]     * inv * TAB_DX;
        float m1 = sh_d[t + 1] * inv * TAB_DX;
        float c2 = 3.0f * (f1 - f0) - 2.0f * m0 - m1;
        float c3 = 2.0f * (f0 - f1) + m0 + m1;
        g_table[s * K_INT + t] = make_float4(f0, m0, c2, c3);
    }
}

__device__ __forceinline__ float cubic_lookup(const float4* __restrict__ tab,
                                              int row_base, float x)
{
    float q  = fmaf(x, TAB_INVDX, TAB_BIAS);   // (x + 6.5) * 8
    float jf = floorf(q);
    jf = fminf(fmaxf(jf, 0.0f), (float)(K_INT - 1));
    float tt = q - jf;
    float4 c = tab[row_base + (int)jf];
    return fmaf(fmaf(fmaf(c.w, tt, c.z), tt, c.y), tt, c.x);
}

// Main kernel: 107.5 KB smem table -> 2 resident blocks/SM (64 warps).
// Latency hiding via warp parallelism; lean loop keeps regs <= 32.
__global__ __launch_bounds__(EVAL_BLOCK, 2)
void eval_kernel(const float* __restrict__ in, const int* __restrict__ idx,
                 float* __restrict__ out, int n4)
{
    extern __shared__ float4 tab[];          // [SUBNETS][ROWP]

    for (int i = threadIdx.x; i < SUBNETS * K_INT; i += EVAL_BLOCK) {
        int s = i / K_INT;
        int j = i - s * K_INT;
        tab[s * ROWP + j] = g_table[i];
    }
    __syncthreads();

    const int tid      = blockIdx.x * EVAL_BLOCK + threadIdx.x;
    const int nthreads = EVAL_GRID * EVAL_BLOCK;

    const int base_s = (tid * 4) & 63;       // multiple of 4, <= 60
    int rowb[4];
    int off[4];
#pragma unroll
    for (int u = 0; u < 4; u++) {
        int s   = base_s + u;                // < 64, no wrap
        rowb[u] = s * ROWP;
        off[u]  = u + idx[s] - s;            // input offset vs 4*i4
    }

    const bool identity = (off[0] == 0) & (off[1] == 1) &
                          (off[2] == 2) & (off[3] == 3);

    if (identity) {
        const float4* __restrict__ in4 = reinterpret_cast<const float4*>(in);
        float4* __restrict__ out4      = reinterpret_cast<float4*>(out);
        for (int i4 = tid; i4 < n4; i4 += nthreads) {
            float4 xv = __ldg(in4 + i4);
            float4 r;
            r.x = cubic_lookup(tab, rowb[0], xv.x);
            r.y = cubic_lookup(tab, rowb[1], xv.y);
            r.z = cubic_lookup(tab, rowb[2], xv.z);
            r.w = cubic_lookup(tab, rowb[3], xv.w);
            out4[i4] = r;
        }
    } else {
        for (int i4 = tid; i4 < n4; i4 += nthreads) {
            const int b4 = i4 << 2;
            float r[4];
#pragma unroll
            for (int u = 0; u < 4; u++) {
                float x = __ldg(in + b4 + off[u]);
                r[u] = cubic_lookup(tab, rowb[u], x);
            }
            reinterpret_cast<float4*>(out)[i4] =
                make_float4(r[0], r[1], r[2], r[3]);
        }
    }
}

extern "C" void kernel_launch(void* const* d_in, const int* in_sizes, int n_in,
                              void* d_out, int out_size)
{
    const float* inputs = (const float*)d_in[0];
    const int*   idx    = (const int*)  d_in[1];
    const float* W1     = (const float*)d_in[2];
    const float* b1     = (const float*)d_in[3];
    const float* W2     = (const float*)d_in[4];
    const float* b2     = (const float*)d_in[5];
    const float* W3     = (const float*)d_in[6];
    const float* b3     = (const float*)d_in[7];
    float*       outp   = (float*)d_out;

    cudaFuncSetAttribute(eval_kernel,
                         cudaFuncAttributeMaxDynamicSharedMemorySize,
                         SMEM_BYTES);

    setup_kernel<<<SUBNETS, 256>>>(W1, b1, W2, b2, W3, b3);

    const int n4 = out_size >> 2;            // 2,097,152
    eval_kernel<<<EVAL_GRID, EVAL_BLOCK, SMEM_BYTES>>>(inputs, idx, outp, n4);
}

// round 5
// speedup vs baseline: 1.5017x; 1.2757x over previous
#include <cuda_runtime.h>
#include <math.h>

#define SUBNETS 64
#define NH1 10
#define NH2 6
#define GRIDN 101
#define K_INT 104            // intervals (delta = 1/8)
#define KNOTS 105            // knots = K_INT + 1
#define TAB_LO  (-6.5f)
#define TAB_DX  (0.125f)     // 1/8
#define TAB_INVDX (8.0f)
#define TAB_BIAS  (52.0f)    // 6.5 * 8

#define EVAL_BLOCK 1024
#define EVAL_GRID  296       // 2 blocks per SM (148 SMs)
#define SMEM_BYTES (SUBNETS * K_INT * (int)sizeof(float4))  // 106,496 B

// Piecewise-cubic table, INTERVAL-MAJOR: g_table[j*64 + s] = (c0,c1,c2,c3)
// for subnet s, interval j. This layout makes warp LDS.128 gathers
// conflict-free: within an 8-lane phase, bank-quad = (j*64+s) mod 8 = s mod 8,
// and each thread owns one subnet (s = tid & 63) so s is 8 consecutive values.
__device__ float4 g_table[K_INT * SUBNETS];

// Accurate MLP evaluation (value + analytic derivative) for one subnet.
__device__ __forceinline__ void mlp_eval(
    float x, int s,
    const float* __restrict__ W1, const float* __restrict__ b1,
    const float* __restrict__ W2, const float* __restrict__ b2,
    const float* __restrict__ W3, const float* __restrict__ b3,
    float* f_out, float* d_out)
{
    float h1[NH1], dh1[NH1];
#pragma unroll
    for (int h = 0; h < NH1; h++) {
        float w = W1[s * NH1 + h];
        float p = fmaf(w, x, b1[s * NH1 + h]);
        float t = tanhf(p);
        h1[h]  = t;
        dh1[h] = (1.0f - t * t) * w;
    }
    float f = b3[s];
    float d = 0.0f;
#pragma unroll
    for (int k = 0; k < NH2; k++) {
        float a  = b2[s * NH2 + k];
        float da = 0.0f;
#pragma unroll
        for (int h = 0; h < NH1; h++) {
            float w2 = W2[(s * NH1 + h) * NH2 + k];
            a  = fmaf(h1[h],  w2, a);
            da = fmaf(dh1[h], w2, da);
        }
        float t  = tanhf(a);
        float w3 = W3[s * NH2 + k];
        f = fmaf(t, w3, f);
        d = fmaf((1.0f - t * t) * da, w3, d);
    }
    *f_out = f;
    *d_out = d;
}

// One block per subnet: grid stats (parallel double reduction) + Hermite
// coefficients with normalization folded in; writes transposed table.
__global__ __launch_bounds__(256)
void setup_kernel(const float* __restrict__ W1, const float* __restrict__ b1,
                  const float* __restrict__ W2, const float* __restrict__ b2,
                  const float* __restrict__ W3, const float* __restrict__ b3)
{
    __shared__ float sh_g[GRIDN];
    __shared__ float sh_f[KNOTS];
    __shared__ float sh_d[KNOTS];
    __shared__ float sh_mean, sh_inv;

    const int s = blockIdx.x;
    const int t = threadIdx.x;

    if (t < GRIDN) {
        float x = fmaf((float)t, 0.02f, -1.0f);   // linspace(-1,1,101)
        float f, d;
        mlp_eval(x, s, W1, b1, W2, b2, W3, b3, &f, &d);
        sh_g[t] = f;
    }
    if (t < KNOTS) {
        float x = fmaf((float)t, TAB_DX, TAB_LO);
        float f, d;
        mlp_eval(x, s, W1, b1, W2, b2, W3, b3, &f, &d);
        sh_f[t] = f;
        sh_d[t] = d;
    }
    __syncthreads();

    // Warp 0: parallel double-precision sum / sumsq over the 101 grid values.
    if (t < 32) {
        double m = 0.0, m2 = 0.0;
        for (int i = t; i < GRIDN; i += 32) {
            double g = (double)sh_g[i];
            m  += g;
            m2 += g * g;
        }
#pragma unroll
        for (int o = 16; o > 0; o >>= 1) {
            m  += __shfl_down_sync(0xFFFFFFFFu, m,  o);
            m2 += __shfl_down_sync(0xFFFFFFFFu, m2, o);
        }
        if (t == 0) {
            m  /= (double)GRIDN;
            m2 /= (double)GRIDN;
            double var = m2 - m * m;
            if (var < 0.0) var = 0.0;
            double sd = sqrt(var);
            if (sd < 1e-10) sd = 1e-10;
            sh_mean = (float)m;
            sh_inv  = (float)(1.0 / sd);
        }
    }
    __syncthreads();

    if (t < K_INT) {
        const float mean = sh_mean;
        const float inv  = sh_inv;
        float f0 = (sh_f[t]     - mean) * inv;
        float f1 = (sh_f[t + 1] - mean) * inv;
        float m0 = sh_d[t]     * inv * TAB_DX;
        float m1 = sh_d[t + 1] * inv * TAB_DX;
        float c2 = 3.0f * (f1 - f0) - 2.0f * m0 - m1;
        float c3 = 2.0f * (f0 - f1) + m0 + m1;
        g_table[t * SUBNETS + s] = make_float4(f0, m0, c2, c3);  // transposed
    }
}

__device__ __forceinline__ float cubic_lookup(const float4* __restrict__ tab,
                                              int s, float x)
{
    float q  = fmaf(x, TAB_INVDX, TAB_BIAS);   // (x + 6.5) * 8
    float jf = floorf(q);
    jf = fminf(fmaxf(jf, 0.0f), (float)(K_INT - 1));
    float tt = q - jf;
    float4 c = tab[(int)jf * SUBNETS + s];
    return fmaf(fmaf(fmaf(c.w, tt, c.z), tt, c.y), tt, c.x);
}

// Main kernel: one subnet per thread (s = tid & 63), fully coalesced
// LDG.32/STG.32, conflict-free LDS.128 table gathers, unroll x4.
__global__ __launch_bounds__(EVAL_BLOCK, 2)
void eval_kernel(const float* __restrict__ in, const int* __restrict__ idx,
                 float* __restrict__ out, int n)
{
    extern __shared__ float4 tab[];          // [K_INT][SUBNETS]

    for (int i = threadIdx.x; i < K_INT * SUBNETS; i += EVAL_BLOCK)
        tab[i] = g_table[i];
    __syncthreads();

    const int tid      = blockIdx.x * EVAL_BLOCK + threadIdx.x;
    const int nthreads = EVAL_GRID * EVAL_BLOCK;     // multiple of 64

    const int s   = tid & 63;
    const int off = idx[s] - s;   // in[b*64 + idx[s]] == in[i + off]

    int i = tid;
    // Unrolled-by-4 grid-stride: independent loads in flight.
    for (; i + 3 * nthreads < n; i += 4 * nthreads) {
        float x0 = __ldg(in + i                + off);
        float x1 = __ldg(in + i +     nthreads + off);
        float x2 = __ldg(in + i + 2 * nthreads + off);
        float x3 = __ldg(in + i + 3 * nthreads + off);
        float r0 = cubic_lookup(tab, s, x0);
        float r1 = cubic_lookup(tab, s, x1);
        float r2 = cubic_lookup(tab, s, x2);
        float r3 = cubic_lookup(tab, s, x3);
        out[i]                = r0;
        out[i +     nthreads] = r1;
        out[i + 2 * nthreads] = r2;
        out[i + 3 * nthreads] = r3;
    }
    for (; i < n; i += nthreads) {
        float x = __ldg(in + i + off);
        out[i] = cubic_lookup(tab, s, x);
    }
}

extern "C" void kernel_launch(void* const* d_in, const int* in_sizes, int n_in,
                              void* d_out, int out_size)
{
    const float* inputs = (const float*)d_in[0];
    const int*   idx    = (const int*)  d_in[1];
    const float* W1     = (const float*)d_in[2];
    const float* b1     = (const float*)d_in[3];
    const float* W2     = (const float*)d_in[4];
    const float* b2     = (const float*)d_in[5];
    const float* W3     = (const float*)d_in[6];
    const float* b3     = (const float*)d_in[7];
    float*       outp   = (float*)d_out;

    cudaFuncSetAttribute(eval_kernel,
                         cudaFuncAttributeMaxDynamicSharedMemorySize,
                         SMEM_BYTES);

    setup_kernel<<<SUBNETS, 256>>>(W1, b1, W2, b2, W3, b3);

    eval_kernel<<<EVAL_GRID, EVAL_BLOCK, SMEM_BYTES>>>(inputs, idx, outp,
                                                       out_size);
}

// round 6
// speedup vs baseline: 1.7588x; 1.1712x over previous
#include <cuda_runtime.h>
#include <math.h>

#define SUBNETS 64
#define NH1 10
#define NH2 6
#define GRIDN 101
#define K_INT 52             // intervals (delta = 1/4)
#define KNOTS 53             // knots = K_INT + 1
#define TAB_LO  (-6.5f)
#define TAB_DX  (0.25f)      // 1/4
#define TAB_INVDX (4.0f)
#define TAB_BIAS  (26.0f)    // 6.5 * 4

#define EVAL_BLOCK 1024
#define EVAL_GRID  296       // 2 blocks per SM (148 SMs)
#define SMEM_BYTES (SUBNETS * K_INT * (int)sizeof(float4))  // 53,248 B

// Piecewise-cubic table, INTERVAL-MAJOR: g_table[j*64 + s] = (c0,c1,c2,c3)
// for subnet s, interval j. Conflict-free warp LDS.128 gathers: within an
// 8-lane phase, bank-quad = (j*64+s) mod 8 = s mod 8, and s = tid & 63 is
// 8 consecutive values per phase.
__device__ float4 g_table[K_INT * SUBNETS];

// Accurate MLP evaluation (value + analytic derivative) for one subnet.
__device__ __forceinline__ void mlp_eval(
    float x, int s,
    const float* __restrict__ W1, const float* __restrict__ b1,
    const float* __restrict__ W2, const float* __restrict__ b2,
    const float* __restrict__ W3, const float* __restrict__ b3,
    float* f_out, float* d_out)
{
    float h1[NH1], dh1[NH1];
#pragma unroll
    for (int h = 0; h < NH1; h++) {
        float w = W1[s * NH1 + h];
        float p = fmaf(w, x, b1[s * NH1 + h]);
        float t = tanhf(p);
        h1[h]  = t;
        dh1[h] = (1.0f - t * t) * w;
    }
    float f = b3[s];
    float d = 0.0f;
#pragma unroll
    for (int k = 0; k < NH2; k++) {
        float a  = b2[s * NH2 + k];
        float da = 0.0f;
#pragma unroll
        for (int h = 0; h < NH1; h++) {
            float w2 = W2[(s * NH1 + h) * NH2 + k];
            a  = fmaf(h1[h],  w2, a);
            da = fmaf(dh1[h], w2, da);
        }
        float t  = tanhf(a);
        float w3 = W3[s * NH2 + k];
        f = fmaf(t, w3, f);
        d = fmaf((1.0f - t * t) * da, w3, d);
    }
    *f_out = f;
    *d_out = d;
}

// One block per subnet: grid stats (parallel double reduction) + Hermite
// coefficients with normalization folded in; writes transposed table.
__global__ __launch_bounds__(256)
void setup_kernel(const float* __restrict__ W1, const float* __restrict__ b1,
                  const float* __restrict__ W2, const float* __restrict__ b2,
                  const float* __restrict__ W3, const float* __restrict__ b3)
{
    __shared__ float sh_g[GRIDN];
    __shared__ float sh_f[KNOTS];
    __shared__ float sh_d[KNOTS];
    __shared__ float sh_mean, sh_inv;

    const int s = blockIdx.x;
    const int t = threadIdx.x;

    if (t < GRIDN) {
        float x = fmaf((float)t, 0.02f, -1.0f);   // linspace(-1,1,101)
        float f, d;
        mlp_eval(x, s, W1, b1, W2, b2, W3, b3, &f, &d);
        sh_g[t] = f;
    }
    if (t < KNOTS) {
        float x = fmaf((float)t, TAB_DX, TAB_LO);
        float f, d;
        mlp_eval(x, s, W1, b1, W2, b2, W3, b3, &f, &d);
        sh_f[t] = f;
        sh_d[t] = d;
    }
    __syncthreads();

    // Warp 0: parallel double-precision sum / sumsq over the 101 grid values.
    if (t < 32) {
        double m = 0.0, m2 = 0.0;
        for (int i = t; i < GRIDN; i += 32) {
            double g = (double)sh_g[i];
            m  += g;
            m2 += g * g;
        }
#pragma unroll
        for (int o = 16; o > 0; o >>= 1) {
            m  += __shfl_down_sync(0xFFFFFFFFu, m,  o);
            m2 += __shfl_down_sync(0xFFFFFFFFu, m2, o);
        }
        if (t == 0) {
            m  /= (double)GRIDN;
            m2 /= (double)GRIDN;
            double var = m2 - m * m;
            if (var < 0.0) var = 0.0;
            double sd = sqrt(var);
            if (sd < 1e-10) sd = 1e-10;
            sh_mean = (float)m;
            sh_inv  = (float)(1.0 / sd);
        }
    }
    __syncthreads();

    if (t < K_INT) {
        const float mean = sh_mean;
        const float inv  = sh_inv;
        float f0 = (sh_f[t]     - mean) * inv;
        float f1 = (sh_f[t + 1] - mean) * inv;
        float m0 = sh_d[t]     * inv * TAB_DX;
        float m1 = sh_d[t + 1] * inv * TAB_DX;
        float c2 = 3.0f * (f1 - f0) - 2.0f * m0 - m1;
        float c3 = 2.0f * (f0 - f1) + m0 + m1;
        g_table[t * SUBNETS + s] = make_float4(f0, m0, c2, c3);  // transposed
    }
}

__device__ __forceinline__ float cubic_lookup(const float4* __restrict__ tab,
                                              int s, float x)
{
    float q  = fmaf(x, TAB_INVDX, TAB_BIAS);   // (x + 6.5) * 4
    float jf = floorf(q);
    jf = fminf(fmaxf(jf, 0.0f), (float)(K_INT - 1));
    float tt = q - jf;
    float4 c = tab[(int)jf * SUBNETS + s];
    return fmaf(fmaf(fmaf(c.w, tt, c.z), tt, c.y), tt, c.x);
}

// Main kernel: one subnet per thread (s = tid & 63), fully coalesced
// LDG.32/STG.32, conflict-free LDS.128 table gathers, unroll x4.
// 53 KB table: fast stage, lots of L1 left as cache for the stream.
__global__ __launch_bounds__(EVAL_BLOCK, 2)
void eval_kernel(const float* __restrict__ in, const int* __restrict__ idx,
                 float* __restrict__ out, int n)
{
    extern __shared__ float4 tab[];          // [K_INT][SUBNETS]

    for (int i = threadIdx.x; i < K_INT * SUBNETS; i += EVAL_BLOCK)
        tab[i] = g_table[i];
    __syncthreads();

    const int tid      = blockIdx.x * EVAL_BLOCK + threadIdx.x;
    const int nthreads = EVAL_GRID * EVAL_BLOCK;     // multiple of 64

    const int s   = tid & 63;
    const int off = idx[s] - s;   // in[b*64 + idx[s]] == in[i + off]

    int i = tid;
    // Unrolled-by-4 grid-stride: independent loads in flight.
    for (; i + 3 * nthreads < n; i += 4 * nthreads) {
        float x0 = __ldg(in + i                + off);
        float x1 = __ldg(in + i +     nthreads + off);
        float x2 = __ldg(in + i + 2 * nthreads + off);
        float x3 = __ldg(in + i + 3 * nthreads + off);
        float r0 = cubic_lookup(tab, s, x0);
        float r1 = cubic_lookup(tab, s, x1);
        float r2 = cubic_lookup(tab, s, x2);
        float r3 = cubic_lookup(tab, s, x3);
        out[i]                = r0;
        out[i +     nthreads] = r1;
        out[i + 2 * nthreads] = r2;
        out[i + 3 * nthreads] = r3;
    }
    for (; i < n; i += nthreads) {
        float x = __ldg(in + i + off);
        out[i] = cubic_lookup(tab, s, x);
    }
}

extern "C" void kernel_launch(void* const* d_in, const int* in_sizes, int n_in,
                              void* d_out, int out_size)
{
    const float* inputs = (const float*)d_in[0];
    const int*   idx    = (const int*)  d_in[1];
    const float* W1     = (const float*)d_in[2];
    const float* b1     = (const float*)d_in[3];
    const float* W2     = (const float*)d_in[4];
    const float* b2     = (const float*)d_in[5];
    const float* W3     = (const float*)d_in[6];
    const float* b3     = (const float*)d_in[7];
    float*       outp   = (float*)d_out;

    cudaFuncSetAttribute(eval_kernel,
                         cudaFuncAttributeMaxDynamicSharedMemorySize,
                         SMEM_BYTES);

    setup_kernel<<<SUBNETS, 256>>>(W1, b1, W2, b2, W3, b3);

    eval_kernel<<<EVAL_GRID, EVAL_BLOCK, SMEM_BYTES>>>(inputs, idx, outp,
                                                       out_size);
}